// round 4
// baseline (speedup 1.0000x reference)
#include <cuda_runtime.h>
#include <cstdint>

#define D_MODEL     1024
#define TPB         256      // each thread owns 4 contiguous channels
#define TOK_PER_BLK 32
#define BUF_TOK     2                        // tokens per TMA chunk
#define NBUF        3                        // buffer ring depth
#define NCHUNK      (TOK_PER_BLK / BUF_TOK)  // 16
#define CHUNK_BYTES (BUF_TOK * D_MODEL * 4)  // 8192

// ---------------------------------------------------------------------------
// out[tok][d] = A[d]*t^2 + B[d]*t + C[d]   (Linear(12->1024) over polynomial
// features collapses to a per-channel quadratic in the token value t).
//
// Stores go via SMEM + cp.async.bulk (TMA) instead of per-thread STG.128:
// one bulk instruction per 8KB row-pair, overlapped with compute of the next
// chunk through a 3-deep buffer ring.
//
// dtype detection (int64 vs int32 tokens): probe first 16 odd 32-bit words;
// int64 (values < 32000, little-endian) -> all zero high-halves.
// ---------------------------------------------------------------------------
__global__ __launch_bounds__(TPB)
void n2_embed_tma_kernel(const void* __restrict__ ntok_raw,
                         const float* __restrict__ W,
                         const float* __restrict__ b,
                         float* __restrict__ out,
                         int n_tok) {
    __shared__ __align__(128) float s_buf[NBUF][BUF_TOK][D_MODEL];
    __shared__ float s_t[TOK_PER_BLK];
    __shared__ int   s_is64;

    const int tid  = threadIdx.x;
    const int tok0 = blockIdx.x * TOK_PER_BLK;
    const int*  pi  = (const int*)ntok_raw;
    const int2* pi2 = (const int2*)ntok_raw;

    // ---- per-block dtype detection (warp 0, L2-broadcast probes) ----
    if (tid < 32) {
        int probe = (tid < 16) ? pi[2 * tid + 1] : 0;
        unsigned any = __ballot_sync(0xFFFFFFFFu, probe != 0);
        if (tid == 0) s_is64 = (any == 0) ? 1 : 0;
    }

    // ---- per-thread coefficients (48 contiguous floats of W) ----
    const int dbase = tid * 4;
    const float4* Wv = (const float4*)(W + (size_t)dbase * 12);
    const float4 bias = *(const float4*)(b + dbase);

    float A[4], B[4], C[4];
#pragma unroll
    for (int c4 = 0; c4 < 4; c4++) {
        float4 f0 = Wv[3 * c4 + 0];   // w0 w1 w2 w3
        float4 f1 = Wv[3 * c4 + 1];   // w4 w5 w6 w7
        float4 f2 = Wv[3 * c4 + 2];   // w8 w9 w10 w11
        A[c4] = f0.x + f0.w + f1.z + f2.y;                   // w0+w3+w6+w9
        B[c4] = f0.y + f0.z + 2.0f * (f1.x + f2.x + f2.z);   // w1+w2+2(w4+w8+w10)
        C[c4] = f0.z + 2.0f * f1.x - f1.y + f2.x + f2.z;     // +bias below
    }
    C[0] += bias.x; C[1] += bias.y; C[2] += bias.z; C[3] += bias.w;

    __syncthreads();   // s_is64 visible

    // ---- load this block's tokens into shared ----
    if (tid < TOK_PER_BLK) {
        int idx = tok0 + tid;
        float t = 0.0f;
        if (idx < n_tok) t = s_is64 ? (float)pi2[idx].x : (float)pi[idx];
        s_t[tid] = t;
    }
    __syncthreads();

    // ---- chunked compute -> SMEM -> TMA bulk store pipeline ----
    for (int c = 0; c < NCHUNK; c++) {
        const int nb = c % NBUF;

        if (c >= NBUF) {   // wait until buffer nb's previous TMA has drained
            if (tid == 0)
                asm volatile("cp.async.bulk.wait_group %0;" :: "n"(NBUF - 1) : "memory");
            __syncthreads();
        }

        const int ctok = tok0 + c * BUF_TOK;

#pragma unroll
        for (int j = 0; j < BUF_TOK; j++) {
            float t = s_t[c * BUF_TOK + j];
            float4 o;
            o.x = fmaf(fmaf(A[0], t, B[0]), t, C[0]);
            o.y = fmaf(fmaf(A[1], t, B[1]), t, C[1]);
            o.z = fmaf(fmaf(A[2], t, B[2]), t, C[2]);
            o.w = fmaf(fmaf(A[3], t, B[3]), t, C[3]);
            *(float4*)&s_buf[nb][j][dbase] = o;
        }
        __syncthreads();   // chunk fully written to SMEM

        if (ctok + BUF_TOK <= n_tok) {
            // full chunk in range -> one bulk store
            if (tid == 0) {
                asm volatile("fence.proxy.async.shared::cta;" ::: "memory");
                uint32_t saddr;
                asm("{ .reg .u64 t; cvta.to.shared.u64 t, %1; cvt.u32.u64 %0, t; }"
                    : "=r"(saddr) : "l"((void*)&s_buf[nb][0][0]));
                void* gptr = (void*)(out + (size_t)ctok * D_MODEL);
                asm volatile(
                    "cp.async.bulk.global.shared::cta.bulk_group [%0], [%1], %2;"
                    :: "l"(gptr), "r"(saddr), "r"((uint32_t)CHUNK_BYTES) : "memory");
                asm volatile("cp.async.bulk.commit_group;" ::: "memory");
            }
        } else {
            // partial tail chunk: fall back to per-thread stores for valid tokens
#pragma unroll
            for (int j = 0; j < BUF_TOK; j++) {
                int tok = ctok + j;
                if (tok < n_tok)
                    *(float4*)(out + (size_t)tok * D_MODEL + dbase) =
                        *(float4*)&s_buf[nb][j][dbase];
            }
        }
    }

    // drain all outstanding bulk stores before CTA exit
    if (tid == 0)
        asm volatile("cp.async.bulk.wait_group 0;" ::: "memory");
}

extern "C" void kernel_launch(void* const* d_in, const int* in_sizes, int n_in,
                              void* d_out, int out_size) {
    const void*  ntok = d_in[0];                 // int64 or int32 tokens [B*S]
    const float* W    = (const float*)d_in[1];   // [D_MODEL, 12] row-major
    const float* b    = (const float*)d_in[2];   // [D_MODEL]
    float* out = (float*)d_out;

    int n_tok = in_sizes[0];                     // 32768
    int grid  = (n_tok + TOK_PER_BLK - 1) / TOK_PER_BLK;  // 1024 blocks

    n2_embed_tma_kernel<<<grid, TPB>>>(ntok, W, b, out, n_tok);
}

// round 5
// speedup vs baseline: 1.1511x; 1.1511x over previous
#include <cuda_runtime.h>
#include <cstdint>

#define D_MODEL 1024
#define TPB     256          // each thread owns 4 contiguous channels
#define GRID    592          // 148 SMs x 4 blocks, single fully-resident wave
#define MAX_TOK_PER_BLK 64   // ceil(32768/592)=56; headroom for other shapes

__device__ float g_A[D_MODEL];
__device__ float g_B[D_MODEL];
__device__ float g_C[D_MODEL];
__device__ int   g_is64;

// ---------------------------------------------------------------------------
// Prologue: collapse Linear(12->1024) over the polynomial feature map
//   feats = [t^2, t, t+1, t^2, 2t+2, -1, t^2, 0, 2t+1, t^2, 2t+1, 0]
// into per-channel quadratic coefficients A,B,C; also detect token dtype.
//   A = w0+w3+w6+w9
//   B = w1+w2+2*(w4+w8+w10)
//   C = w2+2*w4-w5+w8+w10 + b
// dtype: probe first 16 odd 32-bit words; int64 little-endian values < 32000
// have all-zero high halves (P(false positive for int32) ~ 32000^-16).
// ---------------------------------------------------------------------------
__global__ void n2_coeff_kernel(const float* __restrict__ W,
                                const float* __restrict__ b,
                                const int* __restrict__ tok_raw) {
    int d = blockIdx.x * blockDim.x + threadIdx.x;
    if (d < D_MODEL) {
        const float* w = W + (size_t)d * 12;
        float w0 = w[0], w1 = w[1], w2 = w[2], w3 = w[3];
        float w4 = w[4], w5 = w[5], w6 = w[6];
        float w8 = w[8], w9 = w[9], w10 = w[10];
        g_A[d] = w0 + w3 + w6 + w9;
        g_B[d] = w1 + w2 + 2.0f * (w4 + w8 + w10);
        g_C[d] = w2 + 2.0f * w4 - w5 + w8 + w10 + b[d];
    }
    if (blockIdx.x == 0 && threadIdx.x < 32) {
        int probe = (threadIdx.x < 16) ? tok_raw[2 * threadIdx.x + 1] : 0;
        unsigned any = __ballot_sync(0xFFFFFFFFu, probe != 0);
        if (threadIdx.x == 0) g_is64 = (any == 0) ? 1 : 0;
    }
}

// ---------------------------------------------------------------------------
// Main: persistent single-wave kernel. Balanced contiguous token partition,
// tokens staged once into SMEM, then a pure 2xFMA + STG.128 stream.
// L2 traffic ~= output 134MB + coeffs 7MB -> LTS-cap bound.
// ---------------------------------------------------------------------------
__global__ __launch_bounds__(TPB)
void n2_embed_main_kernel(const void* __restrict__ ntok_raw,
                          float4* __restrict__ out,
                          int n_tok) {
    __shared__ float s_t[MAX_TOK_PER_BLK];

    const int tid = threadIdx.x;
    const int bid = blockIdx.x;

    // balanced contiguous partition of n_tok tokens over gridDim.x blocks
    const int grid  = gridDim.x;
    const int q     = n_tok / grid;
    const int rem   = n_tok - q * grid;
    const int base  = q * bid + min(bid, rem);
    const int count = q + (bid < rem ? 1 : 0);

    // stage this block's tokens into shared (one pass, latency paid once)
    if (tid < count) {
        int idx = base + tid;
        float t;
        if (g_is64) t = (float)((const int2*)ntok_raw)[idx].x;  // low word
        else        t = (float)((const int*)ntok_raw)[idx];
        s_t[tid] = t;
    }

    // per-thread coefficients from precomputed globals (12KB hot in L2)
    const int dbase = tid * 4;
    const float4 A = *(const float4*)&g_A[dbase];
    const float4 B = *(const float4*)&g_B[dbase];
    const float4 C = *(const float4*)&g_C[dbase];

    __syncthreads();

    const int row_f4 = D_MODEL / 4;  // 256 float4 per token row
    float4* outp = out + (size_t)base * row_f4 + tid;

    for (int k = 0; k < count; k++) {
        float t = s_t[k];
        float4 o;
        o.x = fmaf(fmaf(A.x, t, B.x), t, C.x);
        o.y = fmaf(fmaf(A.y, t, B.y), t, C.y);
        o.z = fmaf(fmaf(A.z, t, B.z), t, C.z);
        o.w = fmaf(fmaf(A.w, t, B.w), t, C.w);
        __stcs(outp + (size_t)k * row_f4, o);   // evict-first: never re-read
    }
}

extern "C" void kernel_launch(void* const* d_in, const int* in_sizes, int n_in,
                              void* d_out, int out_size) {
    const void*  ntok = d_in[0];                 // int64 or int32 tokens [B*S]
    const float* W    = (const float*)d_in[1];   // [D_MODEL, 12] row-major
    const float* b    = (const float*)d_in[2];   // [D_MODEL]
    float4* out = (float4*)d_out;

    int n_tok = in_sizes[0];                     // 32768

    n2_coeff_kernel<<<(D_MODEL + TPB - 1) / TPB, TPB>>>(W, b, (const int*)ntok);
    n2_embed_main_kernel<<<GRID, TPB>>>(ntok, out, n_tok);
}